// round 5
// baseline (speedup 1.0000x reference)
#include <cuda_runtime.h>
#include <math.h>

#define NN 50000
#define NE 800000
#define HD 256
#define NG 64
#define SCAN_BLKS 196   // ceil(50000/256)

// ---------------- scratch (device globals; no runtime allocation) ----------------
__device__ __align__(16) float g_h [(size_t)NN*HD];   // GEMM output (also S1 [N,128] for attention)
__device__ __align__(16) float g_r [(size_t)NN*HD];   // post agg+relu
__device__ __align__(16) float g_xp[(size_t)NN*HD];   // layer activations
__device__ float g_dinv[NN];
__device__ int   g_cnt[NN];
__device__ int   g_incl[NN];
__device__ int   g_rowptr[NN+1];
__device__ int   g_cursor[NN];
__device__ __align__(16) int2 g_edge[NE];             // {src, coef bits}
__device__ int   g_bsum[SCAN_BLKS];
__device__ int   g_bscan[SCAN_BLKS];
__device__ __align__(16) float g_stat0[HD];
__device__ __align__(16) float g_stat1[HD];
__device__ __align__(16) float g_ain[HD], g_cin[HD];
__device__ __align__(16) float g_A[HD], g_C[HD];
// pre-split tf32 weights: hi and lo parts
__device__ __align__(16) unsigned g_W0h[HD*HD], g_W0l[HD*HD];
__device__ __align__(16) unsigned g_W1h[HD*HD], g_W1l[HD*HD];
__device__ __align__(16) unsigned g_W2h[HD*HD], g_W2l[HD*HD];
__device__ __align__(16) unsigned g_Wa1h[HD*128], g_Wa1l[HD*128];
__device__ __align__(16) float g_cb[HD];
__device__ float g_score[NN], g_w[NN];
__device__ float g_pm[SCAN_BLKS], g_ps[SCAN_BLKS];
__device__ float g_soft[2];
__device__ __align__(16) float g_pooled[NG*HD];
__device__ float g_cntf[NG];

// ---------------- helpers ----------------
__device__ __forceinline__ unsigned f2tf32(float x) {
    unsigned r;
    asm("cvt.rna.tf32.f32 %0, %1;" : "=r"(r) : "f"(x));
    return r;
}

__device__ __forceinline__ void mma_tf32(float* c,
    unsigned a0, unsigned a1, unsigned a2, unsigned a3,
    unsigned b0, unsigned b1)
{
    asm volatile(
        "mma.sync.aligned.m16n8k8.row.col.f32.tf32.tf32.f32 "
        "{%0,%1,%2,%3},{%4,%5,%6,%7},{%8,%9},{%0,%1,%2,%3};\n"
        : "+f"(c[0]), "+f"(c[1]), "+f"(c[2]), "+f"(c[3])
        : "r"(a0), "r"(a1), "r"(a2), "r"(a3), "r"(b0), "r"(b1));
}

// ---------------- input BN stats (column sums over x) ----------------
__global__ void colstats_x(const float* __restrict__ x) {
    int t = threadIdx.x;  // column 0..255
    float s = 0.f, q = 0.f;
    for (int r = blockIdx.x; r < NN; r += gridDim.x) {
        float v = x[(size_t)r*HD + t];
        s += v; q += v*v;
    }
    atomicAdd(&g_stat0[t], s);
    atomicAdd(&g_stat1[t], q);
}

__global__ void finalize_in(const float* __restrict__ g, const float* __restrict__ b) {
    int t = threadIdx.x;
    float m = g_stat0[t] * (1.f/NN);
    float v = g_stat1[t] * (1.f/NN) - m*m;
    float rs = rsqrtf(v + 1e-5f);
    g_ain[t] = rs * g[t];
    g_cin[t] = b[t] - m * rs * g[t];
    g_stat0[t] = 0.f; g_stat1[t] = 0.f;
}

// Fold input BN into W0 (tf32 hi+lo) + folded bias cb
__global__ void fold0(const float* __restrict__ W0) {
    int j = threadIdx.x;
    int k = blockIdx.x;
    if (k < HD) {
        float v = g_ain[k] * W0[k*HD + j];
        unsigned h = f2tf32(v);
        g_W0h[k*HD + j] = h;
        g_W0l[k*HD + j] = f2tf32(v - __uint_as_float(h));
    } else {
        float s = 0.f;
        for (int kk = 0; kk < HD; kk++) s += g_cin[kk] * W0[kk*HD + j];
        g_cb[j] = s;
    }
}

// generic fp32 -> tf32 hi/lo pre-split
__global__ void presplit(const float* __restrict__ src, unsigned* __restrict__ dsth,
                         unsigned* __restrict__ dstl, int n) {
    int i = blockIdx.x*256 + threadIdx.x;
    if (i < n) {
        float v = src[i];
        unsigned h = f2tf32(v);
        dsth[i] = h;
        dstl[i] = f2tf32(v - __uint_as_float(h));
    }
}

// ---------------- degree / CSR build ----------------
__global__ void deg_kernel(const int* __restrict__ dst) {
    for (int e = blockIdx.x*blockDim.x + threadIdx.x; e < NE; e += gridDim.x*blockDim.x)
        atomicAdd(&g_cnt[dst[e]], 1);
}
__global__ void scan1() {   // also computes dinv
    __shared__ int sm[256];
    int t = threadIdx.x;
    int i = blockIdx.x*256 + t;
    int v = (i < NN) ? g_cnt[i] : 0;
    if (i < NN) g_dinv[i] = rsqrtf((float)v + 1.f);
    sm[t] = v; __syncthreads();
    for (int off = 1; off < 256; off <<= 1) {
        int tv = (t >= off) ? sm[t-off] : 0;
        __syncthreads();
        sm[t] += tv;
        __syncthreads();
    }
    if (i < NN) g_incl[i] = sm[t];
    if (t == 255) g_bsum[blockIdx.x] = sm[255];
}
__global__ void scan2() {
    __shared__ int sm[256];
    int t = threadIdx.x;
    sm[t] = (t < SCAN_BLKS) ? g_bsum[t] : 0; __syncthreads();
    for (int off = 1; off < 256; off <<= 1) {
        int tv = (t >= off) ? sm[t-off] : 0;
        __syncthreads();
        sm[t] += tv;
        __syncthreads();
    }
    if (t < SCAN_BLKS) g_bscan[t] = sm[t];
}
__global__ void scan3() {   // also resets g_cnt for next graph replay
    int t = threadIdx.x;
    int i = blockIdx.x*256 + t;
    if (i < NN) {
        int off = (blockIdx.x > 0) ? g_bscan[blockIdx.x-1] : 0;
        int ex = off + g_incl[i] - g_cnt[i];
        g_rowptr[i] = ex;
        g_cursor[i] = ex;
        g_cnt[i] = 0;
    }
    if (i == 0) g_rowptr[NN] = NE;
}
__global__ void fill_kernel(const int* __restrict__ src, const int* __restrict__ dst) {
    for (int e = blockIdx.x*blockDim.x + threadIdx.x; e < NE; e += gridDim.x*blockDim.x) {
        int d = dst[e];
        int s = src[e];
        int p = atomicAdd(&g_cursor[d], 1);
        float cf = g_dinv[s] * g_dinv[d];
        g_edge[p] = make_int2(s, __float_as_int(cf));
    }
}

// ---------------- 3xTF32 tensor-core GEMM v2 ----------------
// Fragment-pair smem layout: uint2 {v[k], v[k+4]} at [lk][ks][row], row-dim padded to 130
// so lk-stride = 520 words = 8 banks -> conflict-free fragment LDS.64.
// Double-buffered smem, one __syncthreads per K-tile.
#define SA_IDX(lk,ks,r) ((lk)*260 + (ks)*130 + (r))
#define SBUF 1040   // uint2 per buffer per array

__global__ __launch_bounds__(256) void tf32_gemm(
    const float* __restrict__ A, const unsigned* __restrict__ Bh,
    const unsigned* __restrict__ Bl,
    const float* __restrict__ bias, float* __restrict__ C, int M, int Nn)
{
    extern __shared__ uint2 smx[];
    uint2* sAh = smx;               // [2][SBUF]
    uint2* sAl = smx + 2*SBUF;
    uint2* sBh = smx + 4*SBUF;
    uint2* sBl = smx + 6*SBUF;

    int tid = threadIdx.x;
    int bm = blockIdx.x*128, bn = blockIdx.y*128;
    int lane = tid & 31, w = tid >> 5;
    int wm = (w >> 2) * 64, wn = (w & 3) * 32;
    int lrow = lane >> 2, lk = lane & 3;

    // A loader: row arow, k-half aks (8 consecutive k)
    int arow = tid >> 1, aks = tid & 1;
    // B loader: k-pair lane lkB, 2 n values at n0
    int lkB = tid >> 6, n0 = (tid & 63) * 2;

    float4 ra0, ra1;
    uint2 rbh[2][2], rbl[2][2];   // [ks][lo/hi row]

    float acc[4][4][4];
    #pragma unroll
    for (int a = 0; a < 4; a++)
        #pragma unroll
        for (int b = 0; b < 4; b++)
            #pragma unroll
            for (int cc = 0; cc < 4; cc++) acc[a][b][cc] = 0.f;

    auto LOADG = [&](int kt) {
        int k0 = kt * 16;
        const float* ap = A + (size_t)(bm+arow)*256 + k0 + aks*8;
        if (bm + arow < M) { ra0 = *(const float4*)ap; ra1 = *(const float4*)(ap+4); }
        else { ra0 = make_float4(0.f,0.f,0.f,0.f); ra1 = ra0; }
        #pragma unroll
        for (int ks = 0; ks < 2; ks++) {
            int klo = k0 + ks*8 + lkB;
            size_t olo = (size_t)klo*Nn + bn + n0;
            size_t ohi = (size_t)(klo+4)*Nn + bn + n0;
            rbh[ks][0] = *(const uint2*)(Bh + olo);
            rbh[ks][1] = *(const uint2*)(Bh + ohi);
            rbl[ks][0] = *(const uint2*)(Bl + olo);
            rbl[ks][1] = *(const uint2*)(Bl + ohi);
        }
    };
    auto STORES = [&](int buf) {
        int bo = buf * SBUF;
        float alo[4] = {ra0.x, ra0.y, ra0.z, ra0.w};
        float ahi[4] = {ra1.x, ra1.y, ra1.z, ra1.w};
        #pragma unroll
        for (int j = 0; j < 4; j++) {
            unsigned hlo = f2tf32(alo[j]);
            unsigned hhi = f2tf32(ahi[j]);
            sAh[bo + SA_IDX(j, aks, arow)] = make_uint2(hlo, hhi);
            unsigned llo = f2tf32(alo[j] - __uint_as_float(hlo));
            unsigned lhi = f2tf32(ahi[j] - __uint_as_float(hhi));
            sAl[bo + SA_IDX(j, aks, arow)] = make_uint2(llo, lhi);
        }
        #pragma unroll
        for (int ks = 0; ks < 2; ks++) {
            *(uint4*)&sBh[bo + SA_IDX(lkB, ks, n0)] =
                make_uint4(rbh[ks][0].x, rbh[ks][1].x, rbh[ks][0].y, rbh[ks][1].y);
            *(uint4*)&sBl[bo + SA_IDX(lkB, ks, n0)] =
                make_uint4(rbl[ks][0].x, rbl[ks][1].x, rbl[ks][0].y, rbl[ks][1].y);
        }
    };

    LOADG(0); STORES(0); __syncthreads();

    for (int kt = 0; kt < 16; kt++) {
        if (kt < 15) LOADG(kt+1);
        int bo = (kt & 1) * SBUF;
        #pragma unroll
        for (int ks = 0; ks < 2; ks++) {
            uint2 aph[4][2], apl[4][2];
            #pragma unroll
            for (int mt = 0; mt < 4; mt++) {
                int m0 = wm + mt*16 + lrow;
                aph[mt][0] = sAh[bo + SA_IDX(lk, ks, m0)];
                aph[mt][1] = sAh[bo + SA_IDX(lk, ks, m0+8)];
                apl[mt][0] = sAl[bo + SA_IDX(lk, ks, m0)];
                apl[mt][1] = sAl[bo + SA_IDX(lk, ks, m0+8)];
            }
            #pragma unroll
            for (int nt = 0; nt < 4; nt++) {
                int nn0 = wn + nt*8 + lrow;
                uint2 bph = sBh[bo + SA_IDX(lk, ks, nn0)];
                uint2 bpl = sBl[bo + SA_IDX(lk, ks, nn0)];
                #pragma unroll
                for (int mt = 0; mt < 4; mt++) {
                    mma_tf32(acc[mt][nt], aph[mt][0].x, aph[mt][1].x, aph[mt][0].y, aph[mt][1].y, bph.x, bph.y);
                    mma_tf32(acc[mt][nt], apl[mt][0].x, apl[mt][1].x, apl[mt][0].y, apl[mt][1].y, bph.x, bph.y);
                    mma_tf32(acc[mt][nt], aph[mt][0].x, aph[mt][1].x, aph[mt][0].y, aph[mt][1].y, bpl.x, bpl.y);
                }
            }
        }
        if (kt < 15) { STORES((kt+1) & 1); __syncthreads(); }
    }

    #pragma unroll
    for (int nt = 0; nt < 4; nt++) {
        int cidx = bn + wn + nt*8 + 2*lk;
        float b0v = bias ? bias[cidx]   : 0.f;
        float b1v = bias ? bias[cidx+1] : 0.f;
        #pragma unroll
        for (int mt = 0; mt < 4; mt++) {
            int r0 = bm + wm + mt*16 + lrow;
            if (r0 < M)
                *(float2*)(C + (size_t)r0*Nn + cidx) =
                    make_float2(acc[mt][nt][0]+b0v, acc[mt][nt][1]+b1v);
            if (r0 + 8 < M)
                *(float2*)(C + (size_t)(r0+8)*Nn + cidx) =
                    make_float2(acc[mt][nt][2]+b0v, acc[mt][nt][3]+b1v);
        }
    }
}

// ---------------- aggregation (column-split) + bias + relu + BN-stat partials ----------------
// Pass handles 128 columns [colbase, colbase+128): h-slice (25MB) stays L2-resident.
__global__ __launch_bounds__(128) void agg_kernel(const float* __restrict__ bias, int colbase) {
    int c = colbase + threadIdx.x;
    int row0 = blockIdx.x * 32;
    float bia = bias[c];
    float ssum = 0.f, ssq = 0.f;
    for (int r = 0; r < 32; r++) {
        int i = row0 + r;
        if (i >= NN) break;
        float di = g_dinv[i];
        float acc = __ldcg(&g_h[(size_t)i*HD + c]) * di * di;
        int p = g_rowptr[i], e = g_rowptr[i+1];
        for (; p + 8 <= e; p += 8) {
            int2 e0 = __ldcs(&g_edge[p]),   e1 = __ldcs(&g_edge[p+1]);
            int2 e2 = __ldcs(&g_edge[p+2]), e3 = __ldcs(&g_edge[p+3]);
            int2 e4 = __ldcs(&g_edge[p+4]), e5 = __ldcs(&g_edge[p+5]);
            int2 e6 = __ldcs(&g_edge[p+6]), e7 = __ldcs(&g_edge[p+7]);
            float v0 = __ldcg(&g_h[(size_t)e0.x*HD + c]);
            float v1 = __ldcg(&g_h[(size_t)e1.x*HD + c]);
            float v2 = __ldcg(&g_h[(size_t)e2.x*HD + c]);
            float v3 = __ldcg(&g_h[(size_t)e3.x*HD + c]);
            float v4 = __ldcg(&g_h[(size_t)e4.x*HD + c]);
            float v5 = __ldcg(&g_h[(size_t)e5.x*HD + c]);
            float v6 = __ldcg(&g_h[(size_t)e6.x*HD + c]);
            float v7 = __ldcg(&g_h[(size_t)e7.x*HD + c]);
            acc = fmaf(v0, __int_as_float(e0.y), acc);
            acc = fmaf(v1, __int_as_float(e1.y), acc);
            acc = fmaf(v2, __int_as_float(e2.y), acc);
            acc = fmaf(v3, __int_as_float(e3.y), acc);
            acc = fmaf(v4, __int_as_float(e4.y), acc);
            acc = fmaf(v5, __int_as_float(e5.y), acc);
            acc = fmaf(v6, __int_as_float(e6.y), acc);
            acc = fmaf(v7, __int_as_float(e7.y), acc);
        }
        for (; p < e; p++) {
            int2 ed = __ldcs(&g_edge[p]);
            acc = fmaf(__ldcg(&g_h[(size_t)ed.x*HD + c]), __int_as_float(ed.y), acc);
        }
        float v = fmaxf(acc + bia, 0.f);
        __stcs(&g_r[(size_t)i*HD + c], v);
        ssum += v; ssq += v*v;
    }
    atomicAdd(&g_stat0[c], ssum);
    atomicAdd(&g_stat1[c], ssq);
}

__global__ void finalize_hidden(const float* __restrict__ g, const float* __restrict__ b) {
    int t = threadIdx.x;
    float m = g_stat0[t] * (1.f/NN);
    float v = g_stat1[t] * (1.f/NN) - m*m;
    float rs = rsqrtf(v + 1e-5f);
    g_A[t] = rs * g[t];
    g_C[t] = b[t] - m * rs * g[t];
    g_stat0[t] = 0.f; g_stat1[t] = 0.f;
}

// xp = r*A + C (+ xp if residual)
__global__ void bnnorm_kernel(int residual) {
    int idx = blockIdx.x*256 + threadIdx.x;       // float4 index
    if (idx >= NN*HD/4) return;
    int c4 = idx & 63;
    float4 v = __ldcs(&((const float4*)g_r)[idx]);
    float4 A = ((const float4*)g_A)[c4];
    float4 C = ((const float4*)g_C)[c4];
    float4 o = make_float4(v.x*A.x+C.x, v.y*A.y+C.y, v.z*A.z+C.z, v.w*A.w+C.w);
    if (residual) {
        float4 p = ((const float4*)g_xp)[idx];
        o.x += p.x; o.y += p.y; o.z += p.z; o.w += p.w;
    }
    ((float4*)g_xp)[idx] = o;
}

// ---------------- attention score ----------------
__global__ __launch_bounds__(128) void score_kernel(const float* __restrict__ Wa2,
                                                    const float* __restrict__ ba2) {
    __shared__ float red[4];
    int j = threadIdx.x;
    float w2 = Wa2[j];
    for (int r = 0; r < 8; r++) {
        int i = blockIdx.x*8 + r;
        float v = g_h[(size_t)i*128 + j];
        v = (v > 0.f) ? v : 0.01f*v;
        float p = v * w2;
        #pragma unroll
        for (int off = 16; off; off >>= 1) p += __shfl_xor_sync(0xffffffffu, p, off);
        if ((j & 31) == 0) red[j >> 5] = p;
        __syncthreads();
        if (j == 0) g_score[i] = red[0]+red[1]+red[2]+red[3] + ba2[0];
        __syncthreads();
    }
}

// ---------------- softmax over all N ----------------
__global__ void smax_part() {
    __shared__ float sm[256], ss[256];
    int t = threadIdx.x;
    float m = -3.4e38f, s = 0.f;
    for (int i = blockIdx.x*256 + t; i < NN; i += SCAN_BLKS*256) {
        float v = g_score[i];
        float nm = fmaxf(m, v);
        float ns = expf(v - nm);
        if (s > 0.f) ns += s * expf(m - nm);
        s = ns; m = nm;
    }
    sm[t] = m; ss[t] = s; __syncthreads();
    for (int off = 128; off; off >>= 1) {
        if (t < off) {
            float m2 = sm[t+off], s2 = ss[t+off];
            float nm = fmaxf(sm[t], m2);
            float acc = 0.f;
            if (ss[t] > 0.f) acc += ss[t] * expf(sm[t] - nm);
            if (s2    > 0.f) acc += s2    * expf(m2    - nm);
            sm[t] = nm; ss[t] = acc;
        }
        __syncthreads();
    }
    if (t == 0) { g_pm[blockIdx.x] = sm[0]; g_ps[blockIdx.x] = ss[0]; }
}
__global__ void smax_final() {
    __shared__ float sm[256], ss[256];
    int t = threadIdx.x;
    sm[t] = (t < SCAN_BLKS) ? g_pm[t] : -3.4e38f;
    ss[t] = (t < SCAN_BLKS) ? g_ps[t] : 0.f;
    __syncthreads();
    for (int off = 128; off; off >>= 1) {
        if (t < off) {
            float m2 = sm[t+off], s2 = ss[t+off];
            float nm = fmaxf(sm[t], m2);
            float acc = 0.f;
            if (ss[t] > 0.f) acc += ss[t] * expf(sm[t] - nm);
            if (s2    > 0.f) acc += s2    * expf(m2    - nm);
            sm[t] = nm; ss[t] = acc;
        }
        __syncthreads();
    }
    if (t == 0) { g_soft[0] = sm[0]; g_soft[1] = 1.f / ss[0]; }
}

__global__ void wcnt_kernel(const int* __restrict__ batch) {
    __shared__ int hist[NG];
    int t = threadIdx.x;
    if (t < NG) hist[t] = 0;
    __syncthreads();
    int i = blockIdx.x*256 + t;
    if (i < NN) {
        g_w[i] = expf(g_score[i] - g_soft[0]) * g_soft[1];
        atomicAdd(&hist[batch[i]], 1);
    }
    __syncthreads();
    if (t < NG && hist[t]) atomicAdd(&g_cntf[t], (float)hist[t]);
}

__global__ __launch_bounds__(256) void pool_kernel(const int* __restrict__ batch) {
    int t = threadIdx.x;   // column
    int row0 = blockIdx.x * 128;
    if (row0 >= NN) return;
    float acc = 0.f;
    int cur = batch[row0];
    for (int r = 0; r < 128; r++) {
        int i = row0 + r;
        if (i >= NN) break;
        int g = batch[i];
        if (g != cur) {
            if (acc != 0.f) atomicAdd(&g_pooled[cur*HD + t], acc);
            acc = 0.f; cur = g;
        }
        acc = fmaf(g_xp[(size_t)i*HD + t], g_w[i], acc);
    }
    atomicAdd(&g_pooled[cur*HD + t], acc);
}

// out[g][o] = (pooled[g]/max(cnt,1)) @ Wo + bo  ; then reset pooled/cntf for next replay
__global__ void final_kernel(const float* __restrict__ Wo, const float* __restrict__ bo,
                             float* __restrict__ out) {
    int t = threadIdx.x;
    float s = 0.f;
    int g = t >> 1, o = t & 1;
    if (t < NG*2) {
        for (int h = 0; h < HD; h++) s = fmaf(g_pooled[g*HD + h], Wo[h*2 + o], s);
        s = s / fmaxf(g_cntf[g], 1.f) + bo[o];
    }
    __syncthreads();   // all reads of pooled/cntf done
    if (t < NG*2) out[t] = s;
    for (int i = t; i < NG*HD; i += 128) g_pooled[i] = 0.f;
    if (t < NG) g_cntf[t] = 0.f;
}

// ---------------- launch ----------------
extern "C" void kernel_launch(void* const* d_in, const int* in_sizes, int n_in,
                              void* d_out, int out_size) {
    const float* x      = (const float*)d_in[0];
    const int*   ei     = (const int*)d_in[1];
    const int*   src    = ei;
    const int*   dst    = ei + NE;
    const int*   batch  = (const int*)d_in[2];
    const float* bing   = (const float*)d_in[3];
    const float* binb   = (const float*)d_in[4];
    const float* W[3]   = {(const float*)d_in[5],  (const float*)d_in[9],  (const float*)d_in[13]};
    const float* bL[3]  = {(const float*)d_in[6],  (const float*)d_in[10], (const float*)d_in[14]};
    const float* bng[3] = {(const float*)d_in[7],  (const float*)d_in[11], (const float*)d_in[15]};
    const float* bnb[3] = {(const float*)d_in[8],  (const float*)d_in[12], (const float*)d_in[16]};
    const float* Wa1    = (const float*)d_in[17];
    const float* ba1    = (const float*)d_in[18];
    const float* Wa2    = (const float*)d_in[19];
    const float* ba2    = (const float*)d_in[20];
    const float* Wo     = (const float*)d_in[21];
    const float* bo     = (const float*)d_in[22];
    float* out = (float*)d_out;

    void* p;
    cudaGetSymbolAddress(&p, g_h);    float* ph   = (float*)p;
    cudaGetSymbolAddress(&p, g_xp);   float* pxp  = (float*)p;
    cudaGetSymbolAddress(&p, g_W0h);  unsigned* pw0h = (unsigned*)p;
    cudaGetSymbolAddress(&p, g_W0l);  unsigned* pw0l = (unsigned*)p;
    cudaGetSymbolAddress(&p, g_W1h);  unsigned* pw1h = (unsigned*)p;
    cudaGetSymbolAddress(&p, g_W1l);  unsigned* pw1l = (unsigned*)p;
    cudaGetSymbolAddress(&p, g_W2h);  unsigned* pw2h = (unsigned*)p;
    cudaGetSymbolAddress(&p, g_W2l);  unsigned* pw2l = (unsigned*)p;
    cudaGetSymbolAddress(&p, g_Wa1h); unsigned* pwah = (unsigned*)p;
    cudaGetSymbolAddress(&p, g_Wa1l); unsigned* pwal = (unsigned*)p;
    cudaGetSymbolAddress(&p, g_cb);   float* pcb  = (float*)p;

    const int GEMM_SMEM = 8 * SBUF * (int)sizeof(uint2);   // 66560 B
    cudaFuncSetAttribute(tf32_gemm, cudaFuncAttributeMaxDynamicSharedMemorySize, GEMM_SMEM);

    dim3 gemm_grid((NN+127)/128, 2);
    int agg_blocks = (NN+31)/32;
    int bn_blocks = (NN*HD/4 + 255)/256;

    colstats_x<<<512,256>>>(x);
    finalize_in<<<1,256>>>(bing, binb);
    fold0<<<HD+1,HD>>>(W[0]);
    tf32_gemm<<<gemm_grid,256,GEMM_SMEM>>>(x, pw0h, pw0l, pcb, ph, NN, HD);   // <- profiled

    // CSR build (independent of GEMM result)
    deg_kernel<<<1024,256>>>(dst);
    scan1<<<SCAN_BLKS,256>>>();
    scan2<<<1,256>>>();
    scan3<<<SCAN_BLKS,256>>>();
    fill_kernel<<<1024,256>>>(src, dst);

    // pre-split remaining weights to tf32 hi/lo
    presplit<<<(HD*HD+255)/256,256>>>(W[1], pw1h, pw1l, HD*HD);
    presplit<<<(HD*HD+255)/256,256>>>(W[2], pw2h, pw2l, HD*HD);
    presplit<<<(HD*128+255)/256,256>>>(Wa1, pwah, pwal, HD*128);

    // layer 0
    agg_kernel<<<agg_blocks,128>>>(bL[0], 0);
    agg_kernel<<<agg_blocks,128>>>(bL[0], 128);
    finalize_hidden<<<1,256>>>(bng[0], bnb[0]);
    bnnorm_kernel<<<bn_blocks,256>>>(0);

    // layers 1,2 with residual
    unsigned* pwsh[3] = {pw0h, pw1h, pw2h};
    unsigned* pwsl[3] = {pw0l, pw1l, pw2l};
    for (int l = 1; l < 3; l++) {
        tf32_gemm<<<gemm_grid,256,GEMM_SMEM>>>(pxp, pwsh[l], pwsl[l], nullptr, ph, NN, HD);
        agg_kernel<<<agg_blocks,128>>>(bL[l], 0);
        agg_kernel<<<agg_blocks,128>>>(bL[l], 128);
        finalize_hidden<<<1,256>>>(bng[l], bnb[l]);
        bnnorm_kernel<<<bn_blocks,256>>>(1);
    }

    // attention
    dim3 attn_grid((NN+127)/128, 1);
    tf32_gemm<<<attn_grid,256,GEMM_SMEM>>>(pxp, pwah, pwal, ba1, ph, NN, 128);
    score_kernel<<<NN/8,128>>>(Wa2, ba2);
    smax_part<<<SCAN_BLKS,256>>>();
    smax_final<<<1,256>>>();
    wcnt_kernel<<<SCAN_BLKS,256>>>(batch);
    pool_kernel<<<(NN+127)/128,256>>>(batch);
    final_kernel<<<1,128>>>(Wo, bo, out);
}

// round 6
// speedup vs baseline: 1.2483x; 1.2483x over previous
#include <cuda_runtime.h>
#include <cuda_bf16.h>
#include <math.h>

#define NN 50000
#define NE 800000
#define HD 256
#define NG 64
#define SCAN_BLKS 196   // ceil(50000/256)

// ---------------- scratch (device globals; no runtime allocation) ----------------
__device__ __align__(16) float g_h [(size_t)NN*HD];   // GEMM output (also S1 [N,128] for attention)
__device__ __align__(16) float g_r [(size_t)NN*HD];   // post agg+relu
__device__ __align__(16) float g_xp[(size_t)NN*HD];   // layer activations
__device__ float g_dinv[NN];
__device__ int   g_cnt[NN];
__device__ int   g_incl[NN];
__device__ int   g_rowptr[NN+1];
__device__ int   g_cursor[NN];
__device__ __align__(16) int2 g_edge[NE];             // {src, coef bits}
__device__ int   g_bsum[SCAN_BLKS];
__device__ int   g_bscan[SCAN_BLKS];
__device__ __align__(16) float g_stat0[HD];
__device__ __align__(16) float g_stat1[HD];
__device__ __align__(16) float g_ain[HD], g_cin[HD];
__device__ __align__(16) float g_A[HD], g_C[HD];
// pre-packed bf16x2 weights (k-pairs packed in one u32): hi and mid parts
__device__ __align__(16) unsigned g_W0h[HD/2*HD], g_W0m[HD/2*HD];
__device__ __align__(16) unsigned g_W1h[HD/2*HD], g_W1m[HD/2*HD];
__device__ __align__(16) unsigned g_W2h[HD/2*HD], g_W2m[HD/2*HD];
__device__ __align__(16) unsigned g_Wa1h[HD/2*128], g_Wa1m[HD/2*128];
__device__ __align__(16) float g_cb[HD];
__device__ float g_score[NN], g_w[NN];
__device__ float g_pm[SCAN_BLKS], g_ps[SCAN_BLKS];
__device__ float g_soft[2];
__device__ __align__(16) float g_pooled[NG*HD];
__device__ float g_cntf[NG];

// ---------------- helpers ----------------
__device__ __forceinline__ unsigned pack_bf16(float lo, float hi) {
    unsigned r;
    asm("cvt.rn.bf16x2.f32 %0, %1, %2;" : "=r"(r) : "f"(hi), "f"(lo));
    return r;
}
__device__ __forceinline__ float bf16rt(float x) {   // round-trip through bf16
    __nv_bfloat16 b = __float2bfloat16_rn(x);
    return __bfloat162float(b);
}
// split x -> (hi, mid) packed pair helper done inline at call sites

__device__ __forceinline__ void mma_bf16(float* c,
    unsigned a0, unsigned a1, unsigned a2, unsigned a3,
    unsigned b0, unsigned b1)
{
    asm volatile(
        "mma.sync.aligned.m16n8k16.row.col.f32.bf16.bf16.f32 "
        "{%0,%1,%2,%3},{%4,%5,%6,%7},{%8,%9},{%0,%1,%2,%3};\n"
        : "+f"(c[0]), "+f"(c[1]), "+f"(c[2]), "+f"(c[3])
        : "r"(a0), "r"(a1), "r"(a2), "r"(a3), "r"(b0), "r"(b1));
}

// ---------------- input BN stats ----------------
__global__ void colstats_x(const float* __restrict__ x) {
    int t = threadIdx.x;
    float s = 0.f, q = 0.f;
    for (int r = blockIdx.x; r < NN; r += gridDim.x) {
        float v = x[(size_t)r*HD + t];
        s += v; q += v*v;
    }
    atomicAdd(&g_stat0[t], s);
    atomicAdd(&g_stat1[t], q);
}

__global__ void finalize_in(const float* __restrict__ g, const float* __restrict__ b) {
    int t = threadIdx.x;
    float m = g_stat0[t] * (1.f/NN);
    float v = g_stat1[t] * (1.f/NN) - m*m;
    float rs = rsqrtf(v + 1e-5f);
    g_ain[t] = rs * g[t];
    g_cin[t] = b[t] - m * rs * g[t];
    g_stat0[t] = 0.f; g_stat1[t] = 0.f;
}

// Fold input BN into W0 (packed bf16x2 hi/mid) + folded bias cb
__global__ void fold0(const float* __restrict__ W0) {
    int j = threadIdx.x;
    int k2 = blockIdx.x;
    if (k2 < HD/2) {
        float v0 = g_ain[2*k2]   * W0[(2*k2)*HD + j];
        float v1 = g_ain[2*k2+1] * W0[(2*k2+1)*HD + j];
        float h0 = bf16rt(v0), h1 = bf16rt(v1);
        g_W0h[k2*HD + j] = pack_bf16(h0, h1);
        g_W0m[k2*HD + j] = pack_bf16(v0 - h0, v1 - h1);
    } else {
        float s = 0.f;
        for (int kk = 0; kk < HD; kk++) s += g_cin[kk] * W0[kk*HD + j];
        g_cb[j] = s;
    }
}

// fp32 [K][Nn] -> packed bf16x2 [K/2][Nn] hi/mid
__global__ void presplit(const float* __restrict__ src, unsigned* __restrict__ dh,
                         unsigned* __restrict__ dm, int Nn, int halfK) {
    int idx = blockIdx.x*256 + threadIdx.x;
    if (idx >= halfK*Nn) return;
    int k2 = idx / Nn, n = idx - k2*Nn;
    float v0 = src[(2*k2)*Nn + n];
    float v1 = src[(2*k2+1)*Nn + n];
    float h0 = bf16rt(v0), h1 = bf16rt(v1);
    dh[idx] = pack_bf16(h0, h1);
    dm[idx] = pack_bf16(v0 - h0, v1 - h1);
}

// ---------------- degree / CSR build ----------------
__global__ void deg_kernel(const int* __restrict__ dst) {
    for (int e = blockIdx.x*blockDim.x + threadIdx.x; e < NE; e += gridDim.x*blockDim.x)
        atomicAdd(&g_cnt[dst[e]], 1);
}
__global__ void scan1() {   // also computes dinv
    __shared__ int sm[256];
    int t = threadIdx.x;
    int i = blockIdx.x*256 + t;
    int v = (i < NN) ? g_cnt[i] : 0;
    if (i < NN) g_dinv[i] = rsqrtf((float)v + 1.f);
    sm[t] = v; __syncthreads();
    for (int off = 1; off < 256; off <<= 1) {
        int tv = (t >= off) ? sm[t-off] : 0;
        __syncthreads();
        sm[t] += tv;
        __syncthreads();
    }
    if (i < NN) g_incl[i] = sm[t];
    if (t == 255) g_bsum[blockIdx.x] = sm[255];
}
__global__ void scan2() {
    __shared__ int sm[256];
    int t = threadIdx.x;
    sm[t] = (t < SCAN_BLKS) ? g_bsum[t] : 0; __syncthreads();
    for (int off = 1; off < 256; off <<= 1) {
        int tv = (t >= off) ? sm[t-off] : 0;
        __syncthreads();
        sm[t] += tv;
        __syncthreads();
    }
    if (t < SCAN_BLKS) g_bscan[t] = sm[t];
}
__global__ void scan3() {   // also resets g_cnt for next graph replay
    int t = threadIdx.x;
    int i = blockIdx.x*256 + t;
    if (i < NN) {
        int off = (blockIdx.x > 0) ? g_bscan[blockIdx.x-1] : 0;
        int ex = off + g_incl[i] - g_cnt[i];
        g_rowptr[i] = ex;
        g_cursor[i] = ex;
        g_cnt[i] = 0;
    }
    if (i == 0) g_rowptr[NN] = NE;
}
__global__ void fill_kernel(const int* __restrict__ src, const int* __restrict__ dst) {
    for (int e = blockIdx.x*blockDim.x + threadIdx.x; e < NE; e += gridDim.x*blockDim.x) {
        int d = dst[e];
        int s = src[e];
        int p = atomicAdd(&g_cursor[d], 1);
        float cf = g_dinv[s] * g_dinv[d];
        g_edge[p] = make_int2(s, __float_as_int(cf));
    }
}

// ---------------- 3xBF16 tensor-core GEMM: C[M,Nn] = A[M,256] @ B[256,Nn] (+bias) ----------------
// A split inline into bf16 hi+mid packed k-pairs; B pre-packed. m16n8k16 MMAs.
// BM=128, BN=128, BK=16 (8 k2 rows), 8 warps (2x4), warp tile 64x32. Double-buffered, 1 sync/tile.
__global__ __launch_bounds__(256) void bf16_gemm(
    const float* __restrict__ A, const unsigned* __restrict__ Bh,
    const unsigned* __restrict__ Bm,
    const float* __restrict__ bias, float* __restrict__ C, int M, int Nn)
{
    __shared__ __align__(16) unsigned sAh[2][8][136], sAm[2][8][136];
    __shared__ __align__(16) unsigned sBh[2][8][136], sBm[2][8][136];

    int tid = threadIdx.x;
    int bm = blockIdx.x*128, bn = blockIdx.y*128;
    int lane = tid & 31, w = tid >> 5;
    int wm = (w >> 2) * 64, wn = (w & 3) * 32;
    int lrow = lane >> 2, tg = lane & 3;

    // A loader: one row, 8 consecutive k (one aks half of the 16-wide tile)
    int arow = tid & 127, aks = tid >> 7;          // aks 0..1
    // B loader: 2 n at bn0, k2 rows bk2 and bk2+4
    int bn0 = (tid & 63) * 2, bk2 = (tid >> 6) & 3;

    float4 ra0, ra1;
    uint2 rbh0, rbh1, rbm0, rbm1;

    float acc[4][4][4];
    #pragma unroll
    for (int a = 0; a < 4; a++)
        #pragma unroll
        for (int b = 0; b < 4; b++)
            #pragma unroll
            for (int cc = 0; cc < 4; cc++) acc[a][b][cc] = 0.f;

    auto LOADG = [&](int kt) {
        const float* ap = A + (size_t)(bm+arow)*256 + kt*16 + aks*8;
        if (bm + arow < M) { ra0 = *(const float4*)ap; ra1 = *(const float4*)(ap+4); }
        else { ra0 = make_float4(0.f,0.f,0.f,0.f); ra1 = ra0; }
        int k2 = kt*8 + bk2;
        size_t o0 = (size_t)k2*Nn + bn + bn0;
        size_t o1 = (size_t)(k2+4)*Nn + bn + bn0;
        rbh0 = *(const uint2*)(Bh + o0); rbh1 = *(const uint2*)(Bh + o1);
        rbm0 = *(const uint2*)(Bm + o0); rbm1 = *(const uint2*)(Bm + o1);
    };
    auto STORES = [&](int buf) {
        float v[8] = {ra0.x, ra0.y, ra0.z, ra0.w, ra1.x, ra1.y, ra1.z, ra1.w};
        #pragma unroll
        for (int j = 0; j < 4; j++) {
            float e = v[2*j], o = v[2*j+1];
            float eh = bf16rt(e), oh = bf16rt(o);
            sAh[buf][aks*4 + j][arow] = pack_bf16(eh, oh);
            sAm[buf][aks*4 + j][arow] = pack_bf16(e - eh, o - oh);
        }
        *(uint2*)&sBh[buf][bk2][bn0]   = rbh0;
        *(uint2*)&sBh[buf][bk2+4][bn0] = rbh1;
        *(uint2*)&sBm[buf][bk2][bn0]   = rbm0;
        *(uint2*)&sBm[buf][bk2+4][bn0] = rbm1;
    };

    LOADG(0); STORES(0); __syncthreads();

    for (int kt = 0; kt < 16; kt++) {
        if (kt < 15) LOADG(kt+1);
        int buf = kt & 1;

        unsigned ah[4][4], am[4][4];
        #pragma unroll
        for (int mt = 0; mt < 4; mt++) {
            int m0 = wm + mt*16 + lrow;
            ah[mt][0] = sAh[buf][tg][m0];     ah[mt][1] = sAh[buf][tg][m0+8];
            ah[mt][2] = sAh[buf][tg+4][m0];   ah[mt][3] = sAh[buf][tg+4][m0+8];
            am[mt][0] = sAm[buf][tg][m0];     am[mt][1] = sAm[buf][tg][m0+8];
            am[mt][2] = sAm[buf][tg+4][m0];   am[mt][3] = sAm[buf][tg+4][m0+8];
        }
        #pragma unroll
        for (int nt = 0; nt < 4; nt++) {
            int n0 = wn + nt*8 + lrow;
            unsigned bh0 = sBh[buf][tg][n0], bh1 = sBh[buf][tg+4][n0];
            unsigned bm0 = sBm[buf][tg][n0], bm1 = sBm[buf][tg+4][n0];
            #pragma unroll
            for (int mt = 0; mt < 4; mt++) {
                mma_bf16(acc[mt][nt], ah[mt][0],ah[mt][1],ah[mt][2],ah[mt][3], bh0, bh1);
                mma_bf16(acc[mt][nt], am[mt][0],am[mt][1],am[mt][2],am[mt][3], bh0, bh1);
                mma_bf16(acc[mt][nt], ah[mt][0],ah[mt][1],ah[mt][2],ah[mt][3], bm0, bm1);
            }
        }
        if (kt < 15) { STORES(buf ^ 1); __syncthreads(); }
    }

    #pragma unroll
    for (int nt = 0; nt < 4; nt++) {
        int cidx = bn + wn + nt*8 + 2*tg;
        float b0v = bias ? bias[cidx]   : 0.f;
        float b1v = bias ? bias[cidx+1] : 0.f;
        #pragma unroll
        for (int mt = 0; mt < 4; mt++) {
            int r0 = bm + wm + mt*16 + lrow;
            if (r0 < M)
                *(float2*)(C + (size_t)r0*Nn + cidx) =
                    make_float2(acc[mt][nt][0]+b0v, acc[mt][nt][1]+b1v);
            if (r0 + 8 < M)
                *(float2*)(C + (size_t)(r0+8)*Nn + cidx) =
                    make_float2(acc[mt][nt][2]+b0v, acc[mt][nt][3]+b1v);
        }
    }
}

// ---------------- aggregation + bias + relu + BN-stat partials (R4-measured version) ----------------
__global__ __launch_bounds__(256) void agg_kernel(const float* __restrict__ bias) {
    int c = threadIdx.x;
    int row0 = blockIdx.x * 32;
    float bia = bias[c];
    float ssum = 0.f, ssq = 0.f;
    for (int r = 0; r < 32; r++) {
        int i = row0 + r;
        if (i >= NN) break;
        float di = g_dinv[i];
        float acc = g_h[(size_t)i*HD + c] * di * di;
        int p = g_rowptr[i], e = g_rowptr[i+1];
        for (; p + 8 <= e; p += 8) {
            int2 e0 = g_edge[p],   e1 = g_edge[p+1];
            int2 e2 = g_edge[p+2], e3 = g_edge[p+3];
            int2 e4 = g_edge[p+4], e5 = g_edge[p+5];
            int2 e6 = g_edge[p+6], e7 = g_edge[p+7];
            float v0 = g_h[(size_t)e0.x*HD + c];
            float v1 = g_h[(size_t)e1.x*HD + c];
            float v2 = g_h[(size_t)e2.x*HD + c];
            float v3 = g_h[(size_t)e3.x*HD + c];
            float v4 = g_h[(size_t)e4.x*HD + c];
            float v5 = g_h[(size_t)e5.x*HD + c];
            float v6 = g_h[(size_t)e6.x*HD + c];
            float v7 = g_h[(size_t)e7.x*HD + c];
            acc = fmaf(v0, __int_as_float(e0.y), acc);
            acc = fmaf(v1, __int_as_float(e1.y), acc);
            acc = fmaf(v2, __int_as_float(e2.y), acc);
            acc = fmaf(v3, __int_as_float(e3.y), acc);
            acc = fmaf(v4, __int_as_float(e4.y), acc);
            acc = fmaf(v5, __int_as_float(e5.y), acc);
            acc = fmaf(v6, __int_as_float(e6.y), acc);
            acc = fmaf(v7, __int_as_float(e7.y), acc);
        }
        for (; p < e; p++) {
            int2 ed = g_edge[p];
            acc = fmaf(g_h[(size_t)ed.x*HD + c], __int_as_float(ed.y), acc);
        }
        float v = fmaxf(acc + bia, 0.f);
        g_r[(size_t)i*HD + c] = v;
        ssum += v; ssq += v*v;
    }
    atomicAdd(&g_stat0[c], ssum);
    atomicAdd(&g_stat1[c], ssq);
}

__global__ void finalize_hidden(const float* __restrict__ g, const float* __restrict__ b) {
    int t = threadIdx.x;
    float m = g_stat0[t] * (1.f/NN);
    float v = g_stat1[t] * (1.f/NN) - m*m;
    float rs = rsqrtf(v + 1e-5f);
    g_A[t] = rs * g[t];
    g_C[t] = b[t] - m * rs * g[t];
    g_stat0[t] = 0.f; g_stat1[t] = 0.f;
}

// xp = r*A + C (+ xp if residual)
__global__ void bnnorm_kernel(int residual) {
    int idx = blockIdx.x*256 + threadIdx.x;       // float4 index
    if (idx >= NN*HD/4) return;
    int c4 = idx & 63;
    float4 v = ((const float4*)g_r)[idx];
    float4 A = ((const float4*)g_A)[c4];
    float4 C = ((const float4*)g_C)[c4];
    float4 o = make_float4(v.x*A.x+C.x, v.y*A.y+C.y, v.z*A.z+C.z, v.w*A.w+C.w);
    if (residual) {
        float4 p = ((const float4*)g_xp)[idx];
        o.x += p.x; o.y += p.y; o.z += p.z; o.w += p.w;
    }
    ((float4*)g_xp)[idx] = o;
}

// ---------------- attention score ----------------
__global__ __launch_bounds__(128) void score_kernel(const float* __restrict__ Wa2,
                                                    const float* __restrict__ ba2) {
    __shared__ float red[4];
    int j = threadIdx.x;
    float w2 = Wa2[j];
    for (int r = 0; r < 8; r++) {
        int i = blockIdx.x*8 + r;
        float v = g_h[(size_t)i*128 + j];
        v = (v > 0.f) ? v : 0.01f*v;
        float p = v * w2;
        #pragma unroll
        for (int off = 16; off; off >>= 1) p += __shfl_xor_sync(0xffffffffu, p, off);
        if ((j & 31) == 0) red[j >> 5] = p;
        __syncthreads();
        if (j == 0) g_score[i] = red[0]+red[1]+red[2]+red[3] + ba2[0];
        __syncthreads();
    }
}

// ---------------- softmax over all N ----------------
__global__ void smax_part() {
    __shared__ float sm[256], ss[256];
    int t = threadIdx.x;
    float m = -3.4e38f, s = 0.f;
    for (int i = blockIdx.x*256 + t; i < NN; i += SCAN_BLKS*256) {
        float v = g_score[i];
        float nm = fmaxf(m, v);
        float ns = expf(v - nm);
        if (s > 0.f) ns += s * expf(m - nm);
        s = ns; m = nm;
    }
    sm[t] = m; ss[t] = s; __syncthreads();
    for (int off = 128; off; off >>= 1) {
        if (t < off) {
            float m2 = sm[t+off], s2 = ss[t+off];
            float nm = fmaxf(sm[t], m2);
            float acc = 0.f;
            if (ss[t] > 0.f) acc += ss[t] * expf(sm[t] - nm);
            if (s2    > 0.f) acc += s2    * expf(m2    - nm);
            sm[t] = nm; ss[t] = acc;
        }
        __syncthreads();
    }
    if (t == 0) { g_pm[blockIdx.x] = sm[0]; g_ps[blockIdx.x] = ss[0]; }
}
__global__ void smax_final() {
    __shared__ float sm[256], ss[256];
    int t = threadIdx.x;
    sm[t] = (t < SCAN_BLKS) ? g_pm[t] : -3.4e38f;
    ss[t] = (t < SCAN_BLKS) ? g_ps[t] : 0.f;
    __syncthreads();
    for (int off = 128; off; off >>= 1) {
        if (t < off) {
            float m2 = sm[t+off], s2 = ss[t+off];
            float nm = fmaxf(sm[t], m2);
            float acc = 0.f;
            if (ss[t] > 0.f) acc += ss[t] * expf(sm[t] - nm);
            if (s2    > 0.f) acc += s2    * expf(m2    - nm);
            sm[t] = nm; ss[t] = acc;
        }
        __syncthreads();
    }
    if (t == 0) { g_soft[0] = sm[0]; g_soft[1] = 1.f / ss[0]; }
}

__global__ void wcnt_kernel(const int* __restrict__ batch) {
    __shared__ int hist[NG];
    int t = threadIdx.x;
    if (t < NG) hist[t] = 0;
    __syncthreads();
    int i = blockIdx.x*256 + t;
    if (i < NN) {
        g_w[i] = expf(g_score[i] - g_soft[0]) * g_soft[1];
        atomicAdd(&hist[batch[i]], 1);
    }
    __syncthreads();
    if (t < NG && hist[t]) atomicAdd(&g_cntf[t], (float)hist[t]);
}

__global__ __launch_bounds__(256) void pool_kernel(const int* __restrict__ batch) {
    int t = threadIdx.x;   // column
    int row0 = blockIdx.x * 128;
    if (row0 >= NN) return;
    float acc = 0.f;
    int cur = batch[row0];
    for (int r = 0; r < 128; r++) {
        int i = row0 + r;
        if (i >= NN) break;
        int g = batch[i];
        if (g != cur) {
            if (acc != 0.f) atomicAdd(&g_pooled[cur*HD + t], acc);
            acc = 0.f; cur = g;
        }
        acc = fmaf(g_xp[(size_t)i*HD + t], g_w[i], acc);
    }
    atomicAdd(&g_pooled[cur*HD + t], acc);
}

// out[g][o] = (pooled[g]/max(cnt,1)) @ Wo + bo  ; then reset pooled/cntf for next replay
__global__ void final_kernel(const float* __restrict__ Wo, const float* __restrict__ bo,
                             float* __restrict__ out) {
    int t = threadIdx.x;
    float s = 0.f;
    int g = t >> 1, o = t & 1;
    if (t < NG*2) {
        for (int h = 0; h < HD; h++) s = fmaf(g_pooled[g*HD + h], Wo[h*2 + o], s);
        s = s / fmaxf(g_cntf[g], 1.f) + bo[o];
    }
    __syncthreads();   // all reads of pooled/cntf done
    if (t < NG*2) out[t] = s;
    for (int i = t; i < NG*HD; i += 128) g_pooled[i] = 0.f;
    if (t < NG) g_cntf[t] = 0.f;
}

// ---------------- launch ----------------
extern "C" void kernel_launch(void* const* d_in, const int* in_sizes, int n_in,
                              void* d_out, int out_size) {
    const float* x      = (const float*)d_in[0];
    const int*   ei     = (const int*)d_in[1];
    const int*   src    = ei;
    const int*   dst    = ei + NE;
    const int*   batch  = (const int*)d_in[2];
    const float* bing   = (const float*)d_in[3];
    const float* binb   = (const float*)d_in[4];
    const float* W[3]   = {(const float*)d_in[5],  (const float*)d_in[9],  (const float*)d_in[13]};
    const float* bL[3]  = {(const float*)d_in[6],  (const float*)d_in[10], (const float*)d_in[14]};
    const float* bng[3] = {(const float*)d_in[7],  (const float*)d_in[11], (const float*)d_in[15]};
    const float* bnb[3] = {(const float*)d_in[8],  (const float*)d_in[12], (const float*)d_in[16]};
    const float* Wa1    = (const float*)d_in[17];
    const float* ba1    = (const float*)d_in[18];
    const float* Wa2    = (const float*)d_in[19];
    const float* ba2    = (const float*)d_in[20];
    const float* Wo     = (const float*)d_in[21];
    const float* bo     = (const float*)d_in[22];
    float* out = (float*)d_out;

    void* p;
    cudaGetSymbolAddress(&p, g_h);    float* ph   = (float*)p;
    cudaGetSymbolAddress(&p, g_xp);   float* pxp  = (float*)p;
    cudaGetSymbolAddress(&p, g_W0h);  unsigned* pw0h = (unsigned*)p;
    cudaGetSymbolAddress(&p, g_W0m);  unsigned* pw0m = (unsigned*)p;
    cudaGetSymbolAddress(&p, g_W1h);  unsigned* pw1h = (unsigned*)p;
    cudaGetSymbolAddress(&p, g_W1m);  unsigned* pw1m = (unsigned*)p;
    cudaGetSymbolAddress(&p, g_W2h);  unsigned* pw2h = (unsigned*)p;
    cudaGetSymbolAddress(&p, g_W2m);  unsigned* pw2m = (unsigned*)p;
    cudaGetSymbolAddress(&p, g_Wa1h); unsigned* pwah = (unsigned*)p;
    cudaGetSymbolAddress(&p, g_Wa1m); unsigned* pwam = (unsigned*)p;
    cudaGetSymbolAddress(&p, g_cb);   float* pcb  = (float*)p;

    dim3 gemm_grid((NN+127)/128, 2);
    int agg_blocks = (NN+31)/32;
    int bn_blocks = (NN*HD/4 + 255)/256;

    colstats_x<<<512,256>>>(x);
    finalize_in<<<1,256>>>(bing, binb);
    fold0<<<HD/2+1,HD>>>(W[0]);
    bf16_gemm<<<gemm_grid,256>>>(x, pw0h, pw0m, pcb, ph, NN, HD);   // <- profiled (4th launch)

    // CSR build (independent of GEMM result)
    deg_kernel<<<1024,256>>>(dst);
    scan1<<<SCAN_BLKS,256>>>();
    scan2<<<1,256>>>();
    scan3<<<SCAN_BLKS,256>>>();
    fill_kernel<<<1024,256>>>(src, dst);

    // pre-pack remaining weights
    presplit<<<(HD/2*HD+255)/256,256>>>(W[1], pw1h, pw1m, HD, HD/2);
    presplit<<<(HD/2*HD+255)/256,256>>>(W[2], pw2h, pw2m, HD, HD/2);
    presplit<<<(HD/2*128+255)/256,256>>>(Wa1, pwah, pwam, 128, HD/2);

    // layer 0
    agg_kernel<<<agg_blocks,256>>>(bL[0]);
    finalize_hidden<<<1,256>>>(bng[0], bnb[0]);
    bnnorm_kernel<<<bn_blocks,256>>>(0);

    // layers 1,2 with residual
    unsigned* pwsh[3] = {pw0h, pw1h, pw2h};
    unsigned* pwsm[3] = {pw0m, pw1m, pw2m};
    for (int l = 1; l < 3; l++) {
        bf16_gemm<<<gemm_grid,256>>>(pxp, pwsh[l], pwsm[l], nullptr, ph, NN, HD);
        agg_kernel<<<agg_blocks,256>>>(bL[l]);
        finalize_hidden<<<1,256>>>(bng[l], bnb[l]);
        bnnorm_kernel<<<bn_blocks,256>>>(1);
    }

    // attention
    dim3 attn_grid((NN+127)/128, 1);
    bf16_gemm<<<attn_grid,256>>>(pxp, pwah, pwam, ba1, ph, NN, 128);
    score_kernel<<<NN/8,128>>>(Wa2, ba2);
    smax_part<<<SCAN_BLKS,256>>>();
    smax_final<<<1,256>>>();
    wcnt_kernel<<<SCAN_BLKS,256>>>(batch);
    pool_kernel<<<(NN+127)/128,256>>>(batch);
    final_kernel<<<1,128>>>(Wo, bo, out);
}

// round 7
// speedup vs baseline: 1.3592x; 1.0889x over previous
#include <cuda_runtime.h>
#include <cuda_bf16.h>
#include <math.h>

#define NN 50000
#define NE 800000
#define HD 256
#define NG 64
#define SCAN_BLKS 196   // ceil(50000/256)

// ---------------- scratch (device globals; no runtime allocation) ----------------
__device__ __align__(16) float g_h [(size_t)NN*HD];   // GEMM output (also S1 [N,128] for attention)
__device__ __align__(16) float g_r [(size_t)NN*HD];   // post agg+relu
__device__ __align__(16) float g_xp[(size_t)NN*HD];   // layer activations
__device__ float g_dinv[NN];
__device__ int   g_cnt[NN];
__device__ int   g_incl[NN];
__device__ int   g_rowptr[NN+1];
__device__ int   g_cursor[NN];
__device__ __align__(16) int2 g_edge[NE];             // {src, coef bits}
__device__ int   g_bsum[SCAN_BLKS];
__device__ int   g_bscan[SCAN_BLKS];
__device__ __align__(16) float g_stat0[HD];
__device__ __align__(16) float g_stat1[HD];
__device__ __align__(16) float g_ain[HD], g_cin[HD];
__device__ __align__(16) float g_A[HD], g_C[HD];
// pre-packed bf16x2 weights TRANSPOSED: [N][K/2] u32 (k-pair packed); hi and mid parts
__device__ __align__(16) unsigned g_W0h[HD*HD/2], g_W0m[HD*HD/2];
__device__ __align__(16) unsigned g_W1h[HD*HD/2], g_W1m[HD*HD/2];
__device__ __align__(16) unsigned g_W2h[HD*HD/2], g_W2m[HD*HD/2];
__device__ __align__(16) unsigned g_Wa1h[128*HD/2], g_Wa1m[128*HD/2];
__device__ __align__(16) float g_cb[HD];
__device__ float g_score[NN], g_w[NN];
__device__ float g_pm[SCAN_BLKS], g_ps[SCAN_BLKS];
__device__ float g_soft[2];
__device__ __align__(16) float g_pooled[NG*HD];
__device__ float g_cntf[NG];

// ---------------- helpers ----------------
__device__ __forceinline__ unsigned pack_bf16(float lo, float hi) {
    unsigned r;
    asm("cvt.rn.bf16x2.f32 %0, %1, %2;" : "=r"(r) : "f"(hi), "f"(lo));
    return r;
}
__device__ __forceinline__ float bf16rt(float x) {
    __nv_bfloat16 b = __float2bfloat16_rn(x);
    return __bfloat162float(b);
}
__device__ __forceinline__ void mma_bf16(float* c,
    unsigned a0, unsigned a1, unsigned a2, unsigned a3,
    unsigned b0, unsigned b1)
{
    asm volatile(
        "mma.sync.aligned.m16n8k16.row.col.f32.bf16.bf16.f32 "
        "{%0,%1,%2,%3},{%4,%5,%6,%7},{%8,%9},{%0,%1,%2,%3};\n"
        : "+f"(c[0]), "+f"(c[1]), "+f"(c[2]), "+f"(c[3])
        : "r"(a0), "r"(a1), "r"(a2), "r"(a3), "r"(b0), "r"(b1));
}
__device__ __forceinline__ void ldsm4(unsigned* r, const void* p) {
    unsigned a = (unsigned)__cvta_generic_to_shared(p);
    asm volatile("ldmatrix.sync.aligned.m8n8.x4.shared.b16 {%0,%1,%2,%3}, [%4];"
        : "=r"(r[0]), "=r"(r[1]), "=r"(r[2]), "=r"(r[3]) : "r"(a));
}
__device__ __forceinline__ unsigned sw128(unsigned b) { return b ^ ((b >> 3) & 0x70u); }

// ---------------- input BN stats ----------------
__global__ void colstats_x(const float* __restrict__ x) {
    int t = threadIdx.x;
    float s = 0.f, q = 0.f;
    for (int r = blockIdx.x; r < NN; r += gridDim.x) {
        float v = x[(size_t)r*HD + t];
        s += v; q += v*v;
    }
    atomicAdd(&g_stat0[t], s);
    atomicAdd(&g_stat1[t], q);
}

__global__ void finalize_in(const float* __restrict__ g, const float* __restrict__ b) {
    int t = threadIdx.x;
    float m = g_stat0[t] * (1.f/NN);
    float v = g_stat1[t] * (1.f/NN) - m*m;
    float rs = rsqrtf(v + 1e-5f);
    g_ain[t] = rs * g[t];
    g_cin[t] = b[t] - m * rs * g[t];
    g_stat0[t] = 0.f; g_stat1[t] = 0.f;
}

// Fold input BN into W0 (transposed packed bf16x2 hi/mid) + folded bias cb
__global__ void fold0(const float* __restrict__ W0) {
    int j = threadIdx.x;      // output column n
    int k2 = blockIdx.x;
    if (k2 < HD/2) {
        float v0 = g_ain[2*k2]   * W0[(2*k2)*HD + j];
        float v1 = g_ain[2*k2+1] * W0[(2*k2+1)*HD + j];
        float h0 = bf16rt(v0), h1 = bf16rt(v1);
        g_W0h[j*(HD/2) + k2] = pack_bf16(h0, h1);
        g_W0m[j*(HD/2) + k2] = pack_bf16(v0 - h0, v1 - h1);
    } else {
        float s = 0.f;
        for (int kk = 0; kk < HD; kk++) s += g_cin[kk] * W0[kk*HD + j];
        g_cb[j] = s;
    }
}

// fp32 [256][Nn] -> transposed packed bf16x2 [Nn][128] hi/mid
__global__ void presplit(const float* __restrict__ src, unsigned* __restrict__ dh,
                         unsigned* __restrict__ dm, int Nn) {
    int idx = blockIdx.x*256 + threadIdx.x;
    if (idx >= Nn*128) return;
    int n = idx >> 7, k2 = idx & 127;
    float v0 = src[(2*k2)*Nn + n];
    float v1 = src[(2*k2+1)*Nn + n];
    float h0 = bf16rt(v0), h1 = bf16rt(v1);
    dh[idx] = pack_bf16(h0, h1);
    dm[idx] = pack_bf16(v0 - h0, v1 - h1);
}

// ---------------- degree / CSR build ----------------
__global__ void deg_kernel(const int* __restrict__ dst) {
    for (int e = blockIdx.x*blockDim.x + threadIdx.x; e < NE; e += gridDim.x*blockDim.x)
        atomicAdd(&g_cnt[dst[e]], 1);
}
__global__ void scan1() {
    __shared__ int sm[256];
    int t = threadIdx.x;
    int i = blockIdx.x*256 + t;
    int v = (i < NN) ? g_cnt[i] : 0;
    if (i < NN) g_dinv[i] = rsqrtf((float)v + 1.f);
    sm[t] = v; __syncthreads();
    for (int off = 1; off < 256; off <<= 1) {
        int tv = (t >= off) ? sm[t-off] : 0;
        __syncthreads();
        sm[t] += tv;
        __syncthreads();
    }
    if (i < NN) g_incl[i] = sm[t];
    if (t == 255) g_bsum[blockIdx.x] = sm[255];
}
__global__ void scan2() {
    __shared__ int sm[256];
    int t = threadIdx.x;
    sm[t] = (t < SCAN_BLKS) ? g_bsum[t] : 0; __syncthreads();
    for (int off = 1; off < 256; off <<= 1) {
        int tv = (t >= off) ? sm[t-off] : 0;
        __syncthreads();
        sm[t] += tv;
        __syncthreads();
    }
    if (t < SCAN_BLKS) g_bscan[t] = sm[t];
}
__global__ void scan3() {
    int t = threadIdx.x;
    int i = blockIdx.x*256 + t;
    if (i < NN) {
        int off = (blockIdx.x > 0) ? g_bscan[blockIdx.x-1] : 0;
        int ex = off + g_incl[i] - g_cnt[i];
        g_rowptr[i] = ex;
        g_cursor[i] = ex;
        g_cnt[i] = 0;
    }
    if (i == 0) g_rowptr[NN] = NE;
}
__global__ void fill_kernel(const int* __restrict__ src, const int* __restrict__ dst) {
    for (int e = blockIdx.x*blockDim.x + threadIdx.x; e < NE; e += gridDim.x*blockDim.x) {
        int d = dst[e];
        int s = src[e];
        int p = atomicAdd(&g_cursor[d], 1);
        float cf = g_dinv[s] * g_dinv[d];
        g_edge[p] = make_int2(s, __float_as_int(cf));
    }
}

// ---------------- 3xBF16 tensor-core GEMM v3 (ldmatrix + SW128-swizzled tiles) ----------------
// A [M,256] fp32 split inline; Bt pre-packed transposed [Nn][128] u32.
// BM=128, BN=128, BK=16, 8 warps (2x4), warp tile 64x32. Double-buffered, 1 sync/tile.
__global__ __launch_bounds__(256) void bf16_gemm(
    const float* __restrict__ A, const unsigned* __restrict__ Bth,
    const unsigned* __restrict__ Btm,
    const float* __restrict__ bias, float* __restrict__ C, int M, int Nn)
{
    __shared__ __align__(16) unsigned char smAh[2][4096], smAm[2][4096];
    __shared__ __align__(16) unsigned char smBh[2][4096], smBm[2][4096];

    int tid = threadIdx.x;
    int bm = blockIdx.x*128, bn = blockIdx.y*128;
    int lane = tid & 31, w = tid >> 5;
    int wm = (w >> 2) * 64, wn = (w & 3) * 32;
    int lr = lane & 15, lh = lane >> 4;
    int lrow = lane >> 2, tg = lane & 3;

    int arow = tid & 127, aks = tid >> 7;     // A: 128 rows x 2 k-halves
    int brow = tid >> 1,  bks = tid & 1;      // B: 128 n-rows x 2 k-halves

    unsigned asw = sw128((unsigned)(arow*32 + aks*16));
    unsigned bsw = sw128((unsigned)(brow*32 + bks*16));

    float4 ra0, ra1;
    uint4 rbh, rbm;

    float acc[4][4][4];
    #pragma unroll
    for (int a = 0; a < 4; a++)
        #pragma unroll
        for (int b = 0; b < 4; b++)
            #pragma unroll
            for (int cc = 0; cc < 4; cc++) acc[a][b][cc] = 0.f;

    auto LOADG = [&](int kt) {
        const float* ap = A + (size_t)(bm+arow)*256 + kt*16 + aks*8;
        if (bm + arow < M) { ra0 = *(const float4*)ap; ra1 = *(const float4*)(ap+4); }
        else { ra0 = make_float4(0.f,0.f,0.f,0.f); ra1 = ra0; }
        size_t bo = (size_t)(bn+brow)*128 + kt*8 + bks*4;
        rbh = *(const uint4*)(Bth + bo);
        rbm = *(const uint4*)(Btm + bo);
    };
    auto STORES = [&](int buf) {
        float v[8] = {ra0.x, ra0.y, ra0.z, ra0.w, ra1.x, ra1.y, ra1.z, ra1.w};
        unsigned hp[4], mp[4];
        #pragma unroll
        for (int j = 0; j < 4; j++) {
            float e = v[2*j], o = v[2*j+1];
            float eh = bf16rt(e), oh = bf16rt(o);
            hp[j] = pack_bf16(eh, oh);
            mp[j] = pack_bf16(e - eh, o - oh);
        }
        *(uint4*)&smAh[buf][asw] = make_uint4(hp[0], hp[1], hp[2], hp[3]);
        *(uint4*)&smAm[buf][asw] = make_uint4(mp[0], mp[1], mp[2], mp[3]);
        *(uint4*)&smBh[buf][bsw] = rbh;
        *(uint4*)&smBm[buf][bsw] = rbm;
    };

    LOADG(0); STORES(0); __syncthreads();

    for (int kt = 0; kt < 16; kt++) {
        if (kt < 15) LOADG(kt+1);
        int buf = kt & 1;

        unsigned ah[4][4], am[4][4], bh[2][4], bmm[2][4];
        #pragma unroll
        for (int mt = 0; mt < 4; mt++) {
            unsigned byte = sw128((unsigned)((wm + mt*16 + lr)*32 + lh*16));
            ldsm4(ah[mt], &smAh[buf][byte]);
            ldsm4(am[mt], &smAm[buf][byte]);
        }
        #pragma unroll
        for (int np = 0; np < 2; np++) {
            unsigned byte = sw128((unsigned)((wn + np*16 + lr)*32 + lh*16));
            ldsm4(bh[np],  &smBh[buf][byte]);
            ldsm4(bmm[np], &smBm[buf][byte]);
        }
        #pragma unroll
        for (int nt = 0; nt < 4; nt++) {
            int np = nt >> 1, sel = nt & 1;
            unsigned b0h = bh[np][sel],  b1h = bh[np][sel+2];
            unsigned b0m = bmm[np][sel], b1m = bmm[np][sel+2];
            #pragma unroll
            for (int mt = 0; mt < 4; mt++) {
                mma_bf16(acc[mt][nt], ah[mt][0],ah[mt][1],ah[mt][2],ah[mt][3], b0h, b1h);
                mma_bf16(acc[mt][nt], am[mt][0],am[mt][1],am[mt][2],am[mt][3], b0h, b1h);
                mma_bf16(acc[mt][nt], ah[mt][0],ah[mt][1],ah[mt][2],ah[mt][3], b0m, b1m);
            }
        }
        if (kt < 15) { STORES(buf ^ 1); __syncthreads(); }
    }

    #pragma unroll
    for (int nt = 0; nt < 4; nt++) {
        int cidx = bn + wn + nt*8 + 2*tg;
        float b0v = bias ? bias[cidx]   : 0.f;
        float b1v = bias ? bias[cidx+1] : 0.f;
        #pragma unroll
        for (int mt = 0; mt < 4; mt++) {
            int r0 = bm + wm + mt*16 + lrow;
            if (r0 < M)
                *(float2*)(C + (size_t)r0*Nn + cidx) =
                    make_float2(acc[mt][nt][0]+b0v, acc[mt][nt][1]+b1v);
            if (r0 + 8 < M)
                *(float2*)(C + (size_t)(r0+8)*Nn + cidx) =
                    make_float2(acc[mt][nt][2]+b0v, acc[mt][nt][3]+b1v);
        }
    }
}

// ---------------- aggregation + bias + relu + BN-stat partials (float2 columns) ----------------
__global__ __launch_bounds__(256) void agg_kernel(const float* __restrict__ bias) {
    int c = (threadIdx.x & 127) * 2;
    int half = threadIdx.x >> 7;
    int row0 = blockIdx.x * 32 + half * 16;
    float2 bia = *(const float2*)&bias[c];
    float ssx=0.f, ssy=0.f, qqx=0.f, qqy=0.f;
    for (int r = 0; r < 16; r++) {
        int i = row0 + r;
        if (i >= NN) break;
        float di = g_dinv[i];
        float2 hv = *(const float2*)&g_h[(size_t)i*HD + c];
        float ax = hv.x * di * di, ay = hv.y * di * di;
        int p = g_rowptr[i], e = g_rowptr[i+1];
        for (; p + 8 <= e; p += 8) {
            int2 e0 = g_edge[p],   e1 = g_edge[p+1];
            int2 e2 = g_edge[p+2], e3 = g_edge[p+3];
            int2 e4 = g_edge[p+4], e5 = g_edge[p+5];
            int2 e6 = g_edge[p+6], e7 = g_edge[p+7];
            float2 v0 = *(const float2*)&g_h[(size_t)e0.x*HD + c];
            float2 v1 = *(const float2*)&g_h[(size_t)e1.x*HD + c];
            float2 v2 = *(const float2*)&g_h[(size_t)e2.x*HD + c];
            float2 v3 = *(const float2*)&g_h[(size_t)e3.x*HD + c];
            float2 v4 = *(const float2*)&g_h[(size_t)e4.x*HD + c];
            float2 v5 = *(const float2*)&g_h[(size_t)e5.x*HD + c];
            float2 v6 = *(const float2*)&g_h[(size_t)e6.x*HD + c];
            float2 v7 = *(const float2*)&g_h[(size_t)e7.x*HD + c];
            float f0 = __int_as_float(e0.y), f1 = __int_as_float(e1.y);
            float f2 = __int_as_float(e2.y), f3 = __int_as_float(e3.y);
            float f4 = __int_as_float(e4.y), f5 = __int_as_float(e5.y);
            float f6 = __int_as_float(e6.y), f7 = __int_as_float(e7.y);
            ax = fmaf(v0.x, f0, ax); ay = fmaf(v0.y, f0, ay);
            ax = fmaf(v1.x, f1, ax); ay = fmaf(v1.y, f1, ay);
            ax = fmaf(v2.x, f2, ax); ay = fmaf(v2.y, f2, ay);
            ax = fmaf(v3.x, f3, ax); ay = fmaf(v3.y, f3, ay);
            ax = fmaf(v4.x, f4, ax); ay = fmaf(v4.y, f4, ay);
            ax = fmaf(v5.x, f5, ax); ay = fmaf(v5.y, f5, ay);
            ax = fmaf(v6.x, f6, ax); ay = fmaf(v6.y, f6, ay);
            ax = fmaf(v7.x, f7, ax); ay = fmaf(v7.y, f7, ay);
        }
        for (; p < e; p++) {
            int2 ed = g_edge[p];
            float2 vv = *(const float2*)&g_h[(size_t)ed.x*HD + c];
            float ff = __int_as_float(ed.y);
            ax = fmaf(vv.x, ff, ax); ay = fmaf(vv.y, ff, ay);
        }
        float vx = fmaxf(ax + bia.x, 0.f);
        float vy = fmaxf(ay + bia.y, 0.f);
        *(float2*)&g_r[(size_t)i*HD + c] = make_float2(vx, vy);
        ssx += vx; ssy += vy; qqx += vx*vx; qqy += vy*vy;
    }
    atomicAdd(&g_stat0[c],   ssx);
    atomicAdd(&g_stat0[c+1], ssy);
    atomicAdd(&g_stat1[c],   qqx);
    atomicAdd(&g_stat1[c+1], qqy);
}

__global__ void finalize_hidden(const float* __restrict__ g, const float* __restrict__ b) {
    int t = threadIdx.x;
    float m = g_stat0[t] * (1.f/NN);
    float v = g_stat1[t] * (1.f/NN) - m*m;
    float rs = rsqrtf(v + 1e-5f);
    g_A[t] = rs * g[t];
    g_C[t] = b[t] - m * rs * g[t];
    g_stat0[t] = 0.f; g_stat1[t] = 0.f;
}

// xp = r*A + C (+ xp if residual)
__global__ void bnnorm_kernel(int residual) {
    int idx = blockIdx.x*256 + threadIdx.x;
    if (idx >= NN*HD/4) return;
    int c4 = idx & 63;
    float4 v = ((const float4*)g_r)[idx];
    float4 A = ((const float4*)g_A)[c4];
    float4 C = ((const float4*)g_C)[c4];
    float4 o = make_float4(v.x*A.x+C.x, v.y*A.y+C.y, v.z*A.z+C.z, v.w*A.w+C.w);
    if (residual) {
        float4 p = ((const float4*)g_xp)[idx];
        o.x += p.x; o.y += p.y; o.z += p.z; o.w += p.w;
    }
    ((float4*)g_xp)[idx] = o;
}

// ---------------- attention score ----------------
__global__ __launch_bounds__(128) void score_kernel(const float* __restrict__ Wa2,
                                                    const float* __restrict__ ba2) {
    __shared__ float red[4];
    int j = threadIdx.x;
    float w2 = Wa2[j];
    for (int r = 0; r < 8; r++) {
        int i = blockIdx.x*8 + r;
        float v = g_h[(size_t)i*128 + j];
        v = (v > 0.f) ? v : 0.01f*v;
        float p = v * w2;
        #pragma unroll
        for (int off = 16; off; off >>= 1) p += __shfl_xor_sync(0xffffffffu, p, off);
        if ((j & 31) == 0) red[j >> 5] = p;
        __syncthreads();
        if (j == 0) g_score[i] = red[0]+red[1]+red[2]+red[3] + ba2[0];
        __syncthreads();
    }
}

// ---------------- softmax over all N ----------------
__global__ void smax_part() {
    __shared__ float sm[256], ss[256];
    int t = threadIdx.x;
    float m = -3.4e38f, s = 0.f;
    for (int i = blockIdx.x*256 + t; i < NN; i += SCAN_BLKS*256) {
        float v = g_score[i];
        float nm = fmaxf(m, v);
        float ns = expf(v - nm);
        if (s > 0.f) ns += s * expf(m - nm);
        s = ns; m = nm;
    }
    sm[t] = m; ss[t] = s; __syncthreads();
    for (int off = 128; off; off >>= 1) {
        if (t < off) {
            float m2 = sm[t+off], s2 = ss[t+off];
            float nm = fmaxf(sm[t], m2);
            float acc = 0.f;
            if (ss[t] > 0.f) acc += ss[t] * expf(sm[t] - nm);
            if (s2    > 0.f) acc += s2    * expf(m2    - nm);
            sm[t] = nm; ss[t] = acc;
        }
        __syncthreads();
    }
    if (t == 0) { g_pm[blockIdx.x] = sm[0]; g_ps[blockIdx.x] = ss[0]; }
}
__global__ void smax_final() {
    __shared__ float sm[256], ss[256];
    int t = threadIdx.x;
    sm[t] = (t < SCAN_BLKS) ? g_pm[t] : -3.4e38f;
    ss[t] = (t < SCAN_BLKS) ? g_ps[t] : 0.f;
    __syncthreads();
    for (int off = 128; off; off >>= 1) {
        if (t < off) {
            float m2 = sm[t+off], s2 = ss[t+off];
            float nm = fmaxf(sm[t], m2);
            float acc = 0.f;
            if (ss[t] > 0.f) acc += ss[t] * expf(sm[t] - nm);
            if (s2    > 0.f) acc += s2    * expf(m2    - nm);
            sm[t] = nm; ss[t] = acc;
        }
        __syncthreads();
    }
    if (t == 0) { g_soft[0] = sm[0]; g_soft[1] = 1.f / ss[0]; }
}

__global__ void wcnt_kernel(const int* __restrict__ batch) {
    __shared__ int hist[NG];
    int t = threadIdx.x;
    if (t < NG) hist[t] = 0;
    __syncthreads();
    int i = blockIdx.x*256 + t;
    if (i < NN) {
        g_w[i] = expf(g_score[i] - g_soft[0]) * g_soft[1];
        atomicAdd(&hist[batch[i]], 1);
    }
    __syncthreads();
    if (t < NG && hist[t]) atomicAdd(&g_cntf[t], (float)hist[t]);
}

__global__ __launch_bounds__(256) void pool_kernel(const int* __restrict__ batch) {
    int t = threadIdx.x;
    int row0 = blockIdx.x * 128;
    if (row0 >= NN) return;
    float acc = 0.f;
    int cur = batch[row0];
    for (int r = 0; r < 128; r++) {
        int i = row0 + r;
        if (i >= NN) break;
        int g = batch[i];
        if (g != cur) {
            if (acc != 0.f) atomicAdd(&g_pooled[cur*HD + t], acc);
            acc = 0.f; cur = g;
        }
        acc = fmaf(g_xp[(size_t)i*HD + t], g_w[i], acc);
    }
    atomicAdd(&g_pooled[cur*HD + t], acc);
}

__global__ void final_kernel(const float* __restrict__ Wo, const float* __restrict__ bo,
                             float* __restrict__ out) {
    int t = threadIdx.x;
    float s = 0.f;
    int g = t >> 1, o = t & 1;
    if (t < NG*2) {
        for (int h = 0; h < HD; h++) s = fmaf(g_pooled[g*HD + h], Wo[h*2 + o], s);
        s = s / fmaxf(g_cntf[g], 1.f) + bo[o];
    }
    __syncthreads();
    if (t < NG*2) out[t] = s;
    for (int i = t; i < NG*HD; i += 128) g_pooled[i] = 0.f;
    if (t < NG) g_cntf[t] = 0.f;
}

// ---------------- launch ----------------
extern "C" void kernel_launch(void* const* d_in, const int* in_sizes, int n_in,
                              void* d_out, int out_size) {
    const float* x      = (const float*)d_in[0];
    const int*   ei     = (const int*)d_in[1];
    const int*   src    = ei;
    const int*   dst    = ei + NE;
    const int*   batch  = (const int*)d_in[2];
    const float* bing   = (const float*)d_in[3];
    const float* binb   = (const float*)d_in[4];
    const float* W[3]   = {(const float*)d_in[5],  (const float*)d_in[9],  (const float*)d_in[13]};
    const float* bL[3]  = {(const float*)d_in[6],  (const float*)d_in[10], (const float*)d_in[14]};
    const float* bng[3] = {(const float*)d_in[7],  (const float*)d_in[11], (const float*)d_in[15]};
    const float* bnb[3] = {(const float*)d_in[8],  (const float*)d_in[12], (const float*)d_in[16]};
    const float* Wa1    = (const float*)d_in[17];
    const float* ba1    = (const float*)d_in[18];
    const float* Wa2    = (const float*)d_in[19];
    const float* ba2    = (const float*)d_in[20];
    const float* Wo     = (const float*)d_in[21];
    const float* bo     = (const float*)d_in[22];
    float* out = (float*)d_out;

    void* p;
    cudaGetSymbolAddress(&p, g_h);    float* ph   = (float*)p;
    cudaGetSymbolAddress(&p, g_xp);   float* pxp  = (float*)p;
    cudaGetSymbolAddress(&p, g_W0h);  unsigned* pw0h = (unsigned*)p;
    cudaGetSymbolAddress(&p, g_W0m);  unsigned* pw0m = (unsigned*)p;
    cudaGetSymbolAddress(&p, g_W1h);  unsigned* pw1h = (unsigned*)p;
    cudaGetSymbolAddress(&p, g_W1m);  unsigned* pw1m = (unsigned*)p;
    cudaGetSymbolAddress(&p, g_W2h);  unsigned* pw2h = (unsigned*)p;
    cudaGetSymbolAddress(&p, g_W2m);  unsigned* pw2m = (unsigned*)p;
    cudaGetSymbolAddress(&p, g_Wa1h); unsigned* pwah = (unsigned*)p;
    cudaGetSymbolAddress(&p, g_Wa1m); unsigned* pwam = (unsigned*)p;
    cudaGetSymbolAddress(&p, g_cb);   float* pcb  = (float*)p;

    dim3 gemm_grid((NN+127)/128, 2);
    int agg_blocks = (NN+31)/32;
    int bn_blocks = (NN*HD/4 + 255)/256;

    colstats_x<<<512,256>>>(x);
    finalize_in<<<1,256>>>(bing, binb);
    fold0<<<HD/2+1,HD>>>(W[0]);
    bf16_gemm<<<gemm_grid,256>>>(x, pw0h, pw0m, pcb, ph, NN, HD);   // <- profiled (4th launch)

    // CSR build (independent of GEMM result)
    deg_kernel<<<1024,256>>>(dst);
    scan1<<<SCAN_BLKS,256>>>();
    scan2<<<1,256>>>();
    scan3<<<SCAN_BLKS,256>>>();
    fill_kernel<<<1024,256>>>(src, dst);

    // pre-pack remaining weights (transposed)
    presplit<<<(HD*128+255)/256,256>>>(W[1], pw1h, pw1m, HD);
    presplit<<<(HD*128+255)/256,256>>>(W[2], pw2h, pw2m, HD);
    presplit<<<(128*128+255)/256,256>>>(Wa1, pwah, pwam, 128);

    // layer 0
    agg_kernel<<<agg_blocks,256>>>(bL[0]);
    finalize_hidden<<<1,256>>>(bng[0], bnb[0]);
    bnnorm_kernel<<<bn_blocks,256>>>(0);

    // layers 1,2 with residual
    unsigned* pwsh[3] = {pw0h, pw1h, pw2h};
    unsigned* pwsm[3] = {pw0m, pw1m, pw2m};
    for (int l = 1; l < 3; l++) {
        bf16_gemm<<<gemm_grid,256>>>(pxp, pwsh[l], pwsm[l], nullptr, ph, NN, HD);
        agg_kernel<<<agg_blocks,256>>>(bL[l]);
        finalize_hidden<<<1,256>>>(bng[l], bnb[l]);
        bnnorm_kernel<<<bn_blocks,256>>>(1);
    }

    // attention
    dim3 attn_grid((NN+127)/128, 1);
    bf16_gemm<<<attn_grid,256>>>(pxp, pwah, pwam, ba1, ph, NN, 128);
    score_kernel<<<NN/8,128>>>(Wa2, ba2);
    smax_part<<<SCAN_BLKS,256>>>();
    smax_final<<<1,256>>>();
    wcnt_kernel<<<SCAN_BLKS,256>>>(batch);
    pool_kernel<<<(NN+127)/128,256>>>(batch);
    final_kernel<<<1,128>>>(Wo, bo, out);
}